// round 13
// baseline (speedup 1.0000x reference)
#include <cuda_runtime.h>
#include <cuda_fp16.h>
#include <math.h>
#include <stdint.h>

// Problem constants (fixed shapes)
#define B_  8
#define N_  4096
#define C_  256
#define K_  4
#define NK_ (N_ * K_)

#define BM 128
#define BN 64
#define CK 32                    // K per chunk (16 fp16 pairs = 128B row)
#define THREADS 256
#define ZTILES  32               // col tiles per z-half (2048 / 64)
#define CHUNKS  (C_ / CK)        // 8 chunks per col tile
#define QTOT    (ZTILES * CHUNKS)  // 256 chunks per CTA

// smem rows: 16 pairs x 8B = 128B data, padded to 160B (stride 40 words = 8
// banks mod 32 -> conflict-free 8B fragment reads; verified rounds 7/11/12).
#define ROW_BYTES   160
#define A_BYTES     (BM * ROW_BYTES)          // 20480
#define B_BYTES     (BN * ROW_BYTES)          // 10240
#define STAGE_BYTES (A_BYTES + B_BYTES)       // 30720
#define SMEM_TOTAL  (2 * STAGE_BYTES)         // 61440 (x3 CTAs = 184320)

// Packed fp16 hi/lo split: per row, pair p (= k/2) is 8B:
//   {hi[2p], hi[2p+1], lo[2p], lo[2p+1]}  (uint2: x=hi pair, y=lo pair)
// Row = 128 pairs = 1024B. 32 MB scratch.
__device__ uint2 g_pack[(size_t)B_ * N_ * (C_ / 2)];

// Per-half top-4 partials: [half][b][n][4] = (value, index) pairs. 2 MB.
__device__ float2 g_part[(size_t)2 * B_ * N_ * K_];

// ---------------------------------------------------------------------------
__device__ __forceinline__ uint2 pack_pair(float a, float b) {
    __half ha = __float2half_rn(a);
    __half hb = __float2half_rn(b);
    __half la = __float2half_rn(a - __half2float(ha));
    __half lb = __float2half_rn(b - __half2float(hb));
    uint2 r;
    r.x = (uint32_t)__half_as_ushort(ha) | ((uint32_t)__half_as_ushort(hb) << 16);
    r.y = (uint32_t)__half_as_ushort(la) | ((uint32_t)__half_as_ushort(lb) << 16);
    return r;
}

// Kernel 1: row-wise L2 normalize + fp16 hi/lo split + pair pack. Warp/row.
__global__ void normalize_kernel(const float* __restrict__ x) {
    int row  = blockIdx.x * 8 + (threadIdx.x >> 5);
    int lane = threadIdx.x & 31;
    const float4* r = (const float4*)(x + (size_t)row * C_);
    float4 v0 = r[lane];
    float4 v1 = r[lane + 32];
    float s = v0.x * v0.x + v0.y * v0.y + v0.z * v0.z + v0.w * v0.w
            + v1.x * v1.x + v1.y * v1.y + v1.z * v1.z + v1.w * v1.w;
#pragma unroll
    for (int off = 16; off; off >>= 1)
        s += __shfl_xor_sync(0xffffffffu, s, off);
    float nrm = sqrtf(s);
    uint2* o = g_pack + (size_t)row * (C_ / 2);
    o[2 * lane + 0]      = pack_pair(v0.x / nrm, v0.y / nrm);
    o[2 * lane + 1]      = pack_pair(v0.z / nrm, v0.w / nrm);
    o[64 + 2 * lane + 0] = pack_pair(v1.x / nrm, v1.y / nrm);
    o[64 + 2 * lane + 1] = pack_pair(v1.z / nrm, v1.w / nrm);
}

// ---------------------------------------------------------------------------
__device__ __forceinline__ void cp16(uint32_t dst, const void* src) {
    asm volatile("cp.async.ca.shared.global [%0], [%1], 16;\n"
                 :: "r"(dst), "l"(src));
}
__device__ __forceinline__ void cp_commit() {
    asm volatile("cp.async.commit_group;\n");
}
__device__ __forceinline__ void mma_f16(float* c, const uint32_t* a,
                                        uint32_t b0, uint32_t b1) {
    asm volatile(
        "mma.sync.aligned.m16n8k16.row.col.f32.f16.f16.f32 "
        "{%0,%1,%2,%3}, {%4,%5,%6,%7}, {%8,%9}, {%0,%1,%2,%3};\n"
        : "+f"(c[0]), "+f"(c[1]), "+f"(c[2]), "+f"(c[3])
        : "r"(a[0]), "r"(a[1]), "r"(a[2]), "r"(a[3]), "r"(b0), "r"(b1));
}

// ---------------------------------------------------------------------------
// Kernel 2: fused 3-product fp16-split tensor-core sim-GEMM + running top-4.
// fp16 lo captures to 2^-22 -> omitted lo*lo <= 2.4e-7 (verified: 9.2e-7
// total rel_err). 48 mmas per K=32 chunk.
// Grid (32, 8, 2): CTA = 128 rows x one z-half (2048 cols, 32 tiles of 64).
// 8 warps, each owns a FULL 16x64 warp tile (m16n8k16) -> one warp per row.
// Continuous 2-stage cp.async pipeline over 256 chunks of K=32.
// ROUND 13: 3 CTAs/SM (grid is 512 -> lever is live; kernel is stall-bound
// at occ 20%, issue ~48%).
// ---------------------------------------------------------------------------
__global__ __launch_bounds__(THREADS, 3)
void knn_kernel() {
    extern __shared__ char smem_raw[];
    const int b     = blockIdx.y;
    const int row0  = blockIdx.x * BM;
    const int zhalf = blockIdx.z;
    const int zcol0 = zhalf * (ZTILES * BN);
    const uint2* __restrict__ fb = g_pack + (size_t)b * N_ * (C_ / 2);

    const int tid  = threadIdx.x;
    const int warp = tid >> 5;
    const int lane = tid & 31;
    const int gid  = lane >> 2;   // group id 0..7
    const int tq   = lane & 3;    // thread-in-group 0..3
    const int m0   = warp * 16;   // warp's row offset in the CTA tile

    const uint32_t sbase = (uint32_t)__cvta_generic_to_shared(smem_raw);

    const int lr = tid >> 3;      // loader base row
    const int lc = tid & 7;       // loader 16B chunk within the 128B row

    float topv[2][4];
    int   topi[2][4];
#pragma unroll
    for (int i = 0; i < 2; i++)
#pragma unroll
        for (int s = 0; s < 4; s++) { topv[i][s] = -INFINITY; topi[i][s] = 0x7fffffff; }

    float acc[32];
#pragma unroll
    for (int j = 0; j < 32; j++) acc[j] = 0.0f;

    // ---- chunk loader: chunk q -> buffer q&1. Chunk = 16 pairs (K=32). ----
#define LOAD_CHUNK(q)                                                           \
    do {                                                                        \
        const int _pp   = ((q) & 7) * 16;            /* pair offset in row */   \
        const int _col0 = zcol0 + ((q) >> 3) * BN;                              \
        const uint32_t _sA = sbase + ((q) & 1) * STAGE_BYTES;                   \
        const uint32_t _sB = _sA + A_BYTES;                                     \
        _Pragma("unroll")                                                       \
        for (int i = 0; i < 4; i++) {                                           \
            int r = lr + i * 32;                                                \
            cp16(_sA + r * ROW_BYTES + lc * 16,                                 \
                 fb + (size_t)(row0 + r) * (C_ / 2) + _pp + lc * 2);            \
        }                                                                       \
        _Pragma("unroll")                                                       \
        for (int i = 0; i < 2; i++) {                                           \
            int r = lr + i * 32;                                                \
            cp16(_sB + r * ROW_BYTES + lc * 16,                                 \
                 fb + (size_t)(_col0 + r) * (C_ / 2) + _pp + lc * 2);           \
        }                                                                       \
        cp_commit();                                                            \
    } while (0)

    LOAD_CHUNK(0);

    for (int q = 0; q < QTOT; q++) {
        asm volatile("cp.async.wait_group 0;\n" ::: "memory");
        __syncthreads();

        if (q + 1 < QTOT)
            LOAD_CHUNK(q + 1);   // overlaps with compute of chunk q

        // ---- compute chunk q: 2 k16 blocks (pair blocks {0..7},{8..15}) ----
        const char* pA = smem_raw + (q & 1) * STAGE_BYTES;
        const char* pB = pA + A_BYTES;
#pragma unroll
        for (int kp8 = 0; kp8 < 16; kp8 += 8) {
            const char* abase = pA + (m0 + gid) * ROW_BYTES;
            uint2 l0 = *(const uint2*)(abase + (kp8 + tq) * 8);
            uint2 l1 = *(const uint2*)(abase + 8 * ROW_BYTES + (kp8 + tq) * 8);
            uint2 l2 = *(const uint2*)(abase + (kp8 + tq + 4) * 8);
            uint2 l3 = *(const uint2*)(abase + 8 * ROW_BYTES + (kp8 + tq + 4) * 8);
            uint32_t ahi[4] = { l0.x, l1.x, l2.x, l3.x };
            uint32_t alo[4] = { l0.y, l1.y, l2.y, l3.y };
#pragma unroll
            for (int nt = 0; nt < 8; nt++) {
                const char* bb = pB + (nt * 8 + gid) * ROW_BYTES;
                uint2 p0 = *(const uint2*)(bb + (kp8 + tq) * 8);
                uint2 p1 = *(const uint2*)(bb + (kp8 + tq + 4) * 8);
                float* c = acc + nt * 4;
                mma_f16(c, ahi, p0.x, p1.x);   // hi*hi
                mma_f16(c, ahi, p0.y, p1.y);   // hi*lo
                mma_f16(c, alo, p0.x, p1.x);   // lo*hi
            }
        }

        // ---- col tile done: fold acc into top-4, reset acc (no drain) ----
        if ((q & 7) == 7) {
            const int col0 = zcol0 + (q >> 3) * BN;
#pragma unroll
            for (int i = 0; i < 2; i++) {
                const int g = row0 + m0 + gid + i * 8;
#pragma unroll
                for (int nt = 0; nt < 8; nt++) {
#pragma unroll
                    for (int j = 0; j < 2; j++) {
                        int   col = col0 + nt * 8 + 2 * tq + j;
                        float v   = acc[nt * 4 + i * 2 + j];
                        if (col != g && v > topv[i][3]) {
                            if (v > topv[i][0]) {
                                topv[i][3] = topv[i][2]; topi[i][3] = topi[i][2];
                                topv[i][2] = topv[i][1]; topi[i][2] = topi[i][1];
                                topv[i][1] = topv[i][0]; topi[i][1] = topi[i][0];
                                topv[i][0] = v;          topi[i][0] = col;
                            } else if (v > topv[i][1]) {
                                topv[i][3] = topv[i][2]; topi[i][3] = topi[i][2];
                                topv[i][2] = topv[i][1]; topi[i][2] = topi[i][1];
                                topv[i][1] = v;          topi[i][1] = col;
                            } else if (v > topv[i][2]) {
                                topv[i][3] = topv[i][2]; topi[i][3] = topi[i][2];
                                topv[i][2] = v;          topi[i][2] = col;
                            } else {
                                topv[i][3] = v;          topi[i][3] = col;
                            }
                        }
                    }
                }
            }
#pragma unroll
            for (int j = 0; j < 32; j++) acc[j] = 0.0f;
        }
    }
#undef LOAD_CHUNK

    // ---- merge across the 4 lanes of each quad, write per-half partials ----
    // g_part layout: ((zhalf*B + b)*N + row)*4 + s = (value, index)
#pragma unroll
    for (int i = 0; i < 2; i++) {
        const int g = row0 + m0 + gid + i * 8;
        float2* dst = g_part + ((size_t)(zhalf * B_ + b) * N_ + g) * K_;
        int p = 0;
#pragma unroll
        for (int s = 0; s < 4; s++) {
            float cv = (p < 4) ? topv[i][p] : -INFINITY;
            int   ci = (p < 4) ? topi[i][p] : 0x7fffffff;
#pragma unroll
            for (int off = 1; off <= 2; off <<= 1) {
                float ov = __shfl_xor_sync(0xffffffffu, cv, off);
                int   oi = __shfl_xor_sync(0xffffffffu, ci, off);
                if (ov > cv || (ov == cv && oi < ci)) { cv = ov; ci = oi; }
            }
            if (p < 4 && topi[i][p] == ci) p++;   // winner lane pops its list
            if (tq == s) dst[s] = make_float2(cv, (float)ci);
        }
    }
}

// ---------------------------------------------------------------------------
// Kernel 3: merge the two column-half top-4 lists per row, emit edges.
// Half-0 indices < half-1 indices, so value-desc / index-asc tie-break is
// preserved by preferring half 0 on equal values.
// Output layout (float32):
//   [b*2*NK .. ]        : src indices
//   [b*2*NK + NK .. ]   : tgt indices
//   [B*2*NK + b*NK .. ] : weights
// ---------------------------------------------------------------------------
__global__ void merge_kernel(float* __restrict__ out) {
    int idx = blockIdx.x * 256 + threadIdx.x;   // 0 .. B*N-1
    int b = idx >> 12, n = idx & (N_ - 1);
    const float2* p0 = g_part + ((size_t)(0 * B_ + b) * N_ + n) * K_;
    const float2* p1 = g_part + ((size_t)(1 * B_ + b) * N_ + n) * K_;
    const size_t ibase = (size_t)b * 2 * NK_;
    const size_t wbase = (size_t)B_ * 2 * NK_ + (size_t)b * NK_;
    int pa = 0, pb = 0;
#pragma unroll
    for (int s = 0; s < 4; s++) {
        float2 a = p0[pa], c = p1[pb];
        bool takeA = (a.x >= c.x);   // ties -> half 0 (lower index)
        float cv = takeA ? a.x : c.x;
        float ci = takeA ? a.y : c.y;
        if (takeA) pa++; else pb++;
        out[ibase + (size_t)n * K_ + s]       = (float)n;
        out[ibase + NK_ + (size_t)n * K_ + s] = ci;
        out[wbase + (size_t)n * K_ + s]       = cv;
    }
}

// ---------------------------------------------------------------------------
extern "C" void kernel_launch(void* const* d_in, const int* in_sizes, int n_in,
                              void* d_out, int out_size) {
    (void)in_sizes; (void)n_in; (void)out_size;
    const float* x = (const float*)d_in[0];
    float* out = (float*)d_out;

    cudaFuncSetAttribute(knn_kernel,
                         cudaFuncAttributeMaxDynamicSharedMemorySize, SMEM_TOTAL);

    normalize_kernel<<<(B_ * N_) / 8, 256>>>(x);
    dim3 grid(N_ / BM, B_, 2);
    knn_kernel<<<grid, THREADS, SMEM_TOTAL>>>();
    merge_kernel<<<(B_ * N_) / 256, 256>>>(out);
}

// round 14
// speedup vs baseline: 1.2327x; 1.2327x over previous
#include <cuda_runtime.h>
#include <cuda_fp16.h>
#include <math.h>
#include <stdint.h>

// Problem constants (fixed shapes)
#define B_  8
#define N_  4096
#define C_  256
#define K_  4
#define NK_ (N_ * K_)

#define BM 128
#define BN 64
#define CK 32                    // K per chunk (16 fp16 pairs = 128B row)
#define THREADS 256
#define ZTILES  32               // col tiles per z-half (2048 / 64)
#define CHUNKS  (C_ / CK)        // 8 chunks per col tile
#define QTOT    (ZTILES * CHUNKS)  // 256 chunks per CTA

// smem rows: 16 pairs as 8 x 16B units = 128B data, padded to 192B.
// Stride 48 words == 16 banks (mod 32): for LDS.128 (8-lane phases, 4 banks
// per lane), lanes {gid,gid+1}x{tq} cover all 32 banks exactly -> conflict-
// free. (160B stride is conflict-free for LDS.64 but 2-way for LDS.128.)
#define ROW_BYTES   192
#define A_BYTES     (BM * ROW_BYTES)          // 24576
#define B_BYTES     (BN * ROW_BYTES)          // 12288
#define STAGE_BYTES (A_BYTES + B_BYTES)       // 36864
#define SMEM_TOTAL  (2 * STAGE_BYTES)         // 73728 (x2 CTAs = 147456)

// Packed fp16 hi/lo split, FRAGMENT-ORDER layout. Per row: 8 blocks of 16
// pairs; within a block, unit u (16B, u=0..7) holds pairs (p_a, p_b) where
// h = u>>2, j = u&3, p_a = 8h+j, p_b = 8h+j+4, as:
//   {hi(p_a), hi(p_b), lo(p_a), lo(p_b)}  (4 x uint32)
// A thread's whole k16 fragment slice (pairs tq, tq+4 of half h) is then
// ONE 16B unit: u = 4h + tq. 32 MB scratch.
__device__ uint2 g_pack[(size_t)B_ * N_ * (C_ / 2)];

// Per-half top-4 partials: [half][b][n][4] = (value, index) pairs. 2 MB.
__device__ float2 g_part[(size_t)2 * B_ * N_ * K_];

// ---------------------------------------------------------------------------
__device__ __forceinline__ uint2 pack_pair(float a, float b) {
    __half ha = __float2half_rn(a);
    __half hb = __float2half_rn(b);
    __half la = __float2half_rn(a - __half2float(ha));
    __half lb = __float2half_rn(b - __half2float(hb));
    uint2 r;
    r.x = (uint32_t)__half_as_ushort(ha) | ((uint32_t)__half_as_ushort(hb) << 16);
    r.y = (uint32_t)__half_as_ushort(la) | ((uint32_t)__half_as_ushort(lb) << 16);
    return r;
}

// Scatter one pair (k = 2p, 2p+1) into the fragment-order layout.
__device__ __forceinline__ void store_pair(uint32_t* o, int p, float a, float b) {
    uint2 v = pack_pair(a, b);
    int t = p >> 4, r = p & 15;
    int h = r >> 3, j = r & 7;
    int u = 4 * h + (j & 3);
    int slot = j >> 2;                 // 0: p_a, 1: p_b
    int wi = t * 32 + u * 4 + slot;    // uint32 index within the row
    o[wi]     = v.x;                   // hi word
    o[wi + 2] = v.y;                   // lo word
}

// Kernel 1: row-wise L2 normalize + fp16 hi/lo split + fragment-order pack.
__global__ void normalize_kernel(const float* __restrict__ x) {
    int row  = blockIdx.x * 8 + (threadIdx.x >> 5);
    int lane = threadIdx.x & 31;
    const float4* r = (const float4*)(x + (size_t)row * C_);
    float4 v0 = r[lane];
    float4 v1 = r[lane + 32];
    float s = v0.x * v0.x + v0.y * v0.y + v0.z * v0.z + v0.w * v0.w
            + v1.x * v1.x + v1.y * v1.y + v1.z * v1.z + v1.w * v1.w;
#pragma unroll
    for (int off = 16; off; off >>= 1)
        s += __shfl_xor_sync(0xffffffffu, s, off);
    float nrm = sqrtf(s);
    uint32_t* o = (uint32_t*)(g_pack + (size_t)row * (C_ / 2));
    store_pair(o, 2 * lane + 0,  v0.x / nrm, v0.y / nrm);
    store_pair(o, 2 * lane + 1,  v0.z / nrm, v0.w / nrm);
    store_pair(o, 64 + 2 * lane + 0, v1.x / nrm, v1.y / nrm);
    store_pair(o, 64 + 2 * lane + 1, v1.z / nrm, v1.w / nrm);
}

// ---------------------------------------------------------------------------
__device__ __forceinline__ void cp16(uint32_t dst, const void* src) {
    asm volatile("cp.async.ca.shared.global [%0], [%1], 16;\n"
                 :: "r"(dst), "l"(src));
}
__device__ __forceinline__ void cp_commit() {
    asm volatile("cp.async.commit_group;\n");
}
__device__ __forceinline__ void mma_f16(float* c, const uint32_t* a,
                                        uint32_t b0, uint32_t b1) {
    asm volatile(
        "mma.sync.aligned.m16n8k16.row.col.f32.f16.f16.f32 "
        "{%0,%1,%2,%3}, {%4,%5,%6,%7}, {%8,%9}, {%0,%1,%2,%3};\n"
        : "+f"(c[0]), "+f"(c[1]), "+f"(c[2]), "+f"(c[3])
        : "r"(a[0]), "r"(a[1]), "r"(a[2]), "r"(a[3]), "r"(b0), "r"(b1));
}

// ---------------------------------------------------------------------------
// Kernel 2: fused 3-product fp16-split tensor-core sim-GEMM + running top-4.
// ROUND 14: fragment-order gmem layout -> ALL smem fragment reads are
// LDS.128 (10 per k16-block vs 20 LDS.64) attacking the mma-independent
// stall floor. mma order/operands bit-identical to round 12.
// Grid (32, 8, 2): CTA = 128 rows x one z-half (2048 cols, 32 tiles of 64).
// 8 warps, each owns a FULL 16x64 warp tile (m16n8k16) -> one warp per row.
// Continuous 2-stage cp.async pipeline over 256 chunks of K=32.
// ---------------------------------------------------------------------------
__global__ __launch_bounds__(THREADS, 2)
void knn_kernel() {
    extern __shared__ char smem_raw[];
    const int b     = blockIdx.y;
    const int row0  = blockIdx.x * BM;
    const int zhalf = blockIdx.z;
    const int zcol0 = zhalf * (ZTILES * BN);
    const uint2* __restrict__ fb = g_pack + (size_t)b * N_ * (C_ / 2);

    const int tid  = threadIdx.x;
    const int warp = tid >> 5;
    const int lane = tid & 31;
    const int gid  = lane >> 2;   // group id 0..7
    const int tq   = lane & 3;    // thread-in-group 0..3
    const int m0   = warp * 16;   // warp's row offset in the CTA tile

    const uint32_t sbase = (uint32_t)__cvta_generic_to_shared(smem_raw);

    const int lr = tid >> 3;      // loader base row
    const int lc = tid & 7;       // loader 16B unit within the 128B row

    float topv[2][4];
    int   topi[2][4];
#pragma unroll
    for (int i = 0; i < 2; i++)
#pragma unroll
        for (int s = 0; s < 4; s++) { topv[i][s] = -INFINITY; topi[i][s] = 0x7fffffff; }

    float acc[32];
#pragma unroll
    for (int j = 0; j < 32; j++) acc[j] = 0.0f;

    // ---- chunk loader: chunk q -> buffer q&1. Chunk = one 16-pair block.
    //      Verbatim 16B copies; fragment order is baked into gmem. ----
#define LOAD_CHUNK(q)                                                           \
    do {                                                                        \
        const int _pp   = ((q) & 7) * 16;            /* pair offset in row */   \
        const int _col0 = zcol0 + ((q) >> 3) * BN;                              \
        const uint32_t _sA = sbase + ((q) & 1) * STAGE_BYTES;                   \
        const uint32_t _sB = _sA + A_BYTES;                                     \
        _Pragma("unroll")                                                       \
        for (int i = 0; i < 4; i++) {                                           \
            int r = lr + i * 32;                                                \
            cp16(_sA + r * ROW_BYTES + lc * 16,                                 \
                 fb + (size_t)(row0 + r) * (C_ / 2) + _pp + lc * 2);            \
        }                                                                       \
        _Pragma("unroll")                                                       \
        for (int i = 0; i < 2; i++) {                                           \
            int r = lr + i * 32;                                                \
            cp16(_sB + r * ROW_BYTES + lc * 16,                                 \
                 fb + (size_t)(_col0 + r) * (C_ / 2) + _pp + lc * 2);           \
        }                                                                       \
        cp_commit();                                                            \
    } while (0)

    LOAD_CHUNK(0);

    for (int q = 0; q < QTOT; q++) {
        asm volatile("cp.async.wait_group 0;\n" ::: "memory");
        __syncthreads();

        if (q + 1 < QTOT)
            LOAD_CHUNK(q + 1);   // overlaps with compute of chunk q

        // ---- compute chunk q: 2 k16 halves, LDS.128 fragments ----
        const char* pA = smem_raw + (q & 1) * STAGE_BYTES;
        const char* pB = pA + A_BYTES;
#pragma unroll
        for (int h = 0; h < 2; h++) {
            const int uoff = (4 * h + tq) * 16;
            const char* abase = pA + (m0 + gid) * ROW_BYTES + uoff;
            uint4 q0 = *(const uint4*)abase;                    // row gid
            uint4 q1 = *(const uint4*)(abase + 8 * ROW_BYTES);  // row gid+8
            uint32_t ahi[4] = { q0.x, q1.x, q0.y, q1.y };
            uint32_t alo[4] = { q0.z, q1.z, q0.w, q1.w };
#pragma unroll
            for (int nt = 0; nt < 8; nt++) {
                uint4 v = *(const uint4*)(pB + (nt * 8 + gid) * ROW_BYTES + uoff);
                float* c = acc + nt * 4;
                mma_f16(c, ahi, v.x, v.y);   // hi*hi
                mma_f16(c, ahi, v.z, v.w);   // hi*lo
                mma_f16(c, alo, v.x, v.y);   // lo*hi
            }
        }

        // ---- col tile done: fold acc into top-4, reset acc (no drain) ----
        if ((q & 7) == 7) {
            const int col0 = zcol0 + (q >> 3) * BN;
#pragma unroll
            for (int i = 0; i < 2; i++) {
                const int g = row0 + m0 + gid + i * 8;
#pragma unroll
                for (int nt = 0; nt < 8; nt++) {
#pragma unroll
                    for (int j = 0; j < 2; j++) {
                        int   col = col0 + nt * 8 + 2 * tq + j;
                        float v   = acc[nt * 4 + i * 2 + j];
                        if (col != g && v > topv[i][3]) {
                            if (v > topv[i][0]) {
                                topv[i][3] = topv[i][2]; topi[i][3] = topi[i][2];
                                topv[i][2] = topv[i][1]; topi[i][2] = topi[i][1];
                                topv[i][1] = topv[i][0]; topi[i][1] = topi[i][0];
                                topv[i][0] = v;          topi[i][0] = col;
                            } else if (v > topv[i][1]) {
                                topv[i][3] = topv[i][2]; topi[i][3] = topi[i][2];
                                topv[i][2] = topv[i][1]; topi[i][2] = topi[i][1];
                                topv[i][1] = v;          topi[i][1] = col;
                            } else if (v > topv[i][2]) {
                                topv[i][3] = topv[i][2]; topi[i][3] = topi[i][2];
                                topv[i][2] = v;          topi[i][2] = col;
                            } else {
                                topv[i][3] = v;          topi[i][3] = col;
                            }
                        }
                    }
                }
            }
#pragma unroll
            for (int j = 0; j < 32; j++) acc[j] = 0.0f;
        }
    }
#undef LOAD_CHUNK

    // ---- merge across the 4 lanes of each quad, write per-half partials ----
    // g_part layout: ((zhalf*B + b)*N + row)*4 + s = (value, index)
#pragma unroll
    for (int i = 0; i < 2; i++) {
        const int g = row0 + m0 + gid + i * 8;
        float2* dst = g_part + ((size_t)(zhalf * B_ + b) * N_ + g) * K_;
        int p = 0;
#pragma unroll
        for (int s = 0; s < 4; s++) {
            float cv = (p < 4) ? topv[i][p] : -INFINITY;
            int   ci = (p < 4) ? topi[i][p] : 0x7fffffff;
#pragma unroll
            for (int off = 1; off <= 2; off <<= 1) {
                float ov = __shfl_xor_sync(0xffffffffu, cv, off);
                int   oi = __shfl_xor_sync(0xffffffffu, ci, off);
                if (ov > cv || (ov == cv && oi < ci)) { cv = ov; ci = oi; }
            }
            if (p < 4 && topi[i][p] == ci) p++;   // winner lane pops its list
            if (tq == s) dst[s] = make_float2(cv, (float)ci);
        }
    }
}

// ---------------------------------------------------------------------------
// Kernel 3: merge the two column-half top-4 lists per row, emit edges.
// Half-0 indices < half-1 indices, so value-desc / index-asc tie-break is
// preserved by preferring half 0 on equal values.
// Output layout (float32):
//   [b*2*NK .. ]        : src indices
//   [b*2*NK + NK .. ]   : tgt indices
//   [B*2*NK + b*NK .. ] : weights
// ---------------------------------------------------------------------------
__global__ void merge_kernel(float* __restrict__ out) {
    int idx = blockIdx.x * 256 + threadIdx.x;   // 0 .. B*N-1
    int b = idx >> 12, n = idx & (N_ - 1);
    const float2* p0 = g_part + ((size_t)(0 * B_ + b) * N_ + n) * K_;
    const float2* p1 = g_part + ((size_t)(1 * B_ + b) * N_ + n) * K_;
    const size_t ibase = (size_t)b * 2 * NK_;
    const size_t wbase = (size_t)B_ * 2 * NK_ + (size_t)b * NK_;
    int pa = 0, pb = 0;
#pragma unroll
    for (int s = 0; s < 4; s++) {
        float2 a = p0[pa], c = p1[pb];
        bool takeA = (a.x >= c.x);   // ties -> half 0 (lower index)
        float cv = takeA ? a.x : c.x;
        float ci = takeA ? a.y : c.y;
        if (takeA) pa++; else pb++;
        out[ibase + (size_t)n * K_ + s]       = (float)n;
        out[ibase + NK_ + (size_t)n * K_ + s] = ci;
        out[wbase + (size_t)n * K_ + s]       = cv;
    }
}

// ---------------------------------------------------------------------------
extern "C" void kernel_launch(void* const* d_in, const int* in_sizes, int n_in,
                              void* d_out, int out_size) {
    (void)in_sizes; (void)n_in; (void)out_size;
    const float* x = (const float*)d_in[0];
    float* out = (float*)d_out;

    cudaFuncSetAttribute(knn_kernel,
                         cudaFuncAttributeMaxDynamicSharedMemorySize, SMEM_TOTAL);

    normalize_kernel<<<(B_ * N_) / 8, 256>>>(x);
    dim3 grid(N_ / BM, B_, 2);
    knn_kernel<<<grid, THREADS, SMEM_TOTAL>>>();
    merge_kernel<<<(B_ * N_) / 256, 256>>>(out);
}